// round 16
// baseline (speedup 1.0000x reference)
#include <cuda_runtime.h>

// ComponentWiseSpline: rational-quadratic spline flow, forward + log|det J|.
// B=65536 rows, D=128 dims, K=8 interior bins.
// R16: R15 + codegen-fat removal: all-scalar body (no register arrays),
//      peeled-tail loop (unconditional prefetch in main loop), batched
//      reciprocal (1 RCP per row). Same table/search/layout as R15.

#define BB 65536
#define DD 128
#define KK 8
#define NSLOT 9                          // identity | 8 interior
#define NQ (BB / 4)                      // 16384 row-quads
#define BLOCK 512
#define TEAMS 8                          // 2-warp teams per block
#define GRIDB 296                        // 148 SMs * 2 blocks
#define NSQ (GRIDB * TEAMS)              // 2368 quad-streams
#define MAXQ ((NQ + NSQ - 1) / NSQ)      // 7

// overlay: thresholds staging (1152 floats), then partials (1792 floats)
#define AUXN (TEAMS * 2 * MAXQ * 4 * 4)  // 1792 floats = 7 KB
#define PARTBASE(t, h, i) ((((t) * 2 + (h)) * MAXQ + (i)) * 16)

__device__ __forceinline__ float fsetge(float a, float b) {
    float r;
    asm("set.ge.f32.f32 %0, %1, %2;" : "=f"(r) : "f"(a), "f"(b));
    return r;
}

// Per-row body: 2 adjacent dims (c0/c1), batched reciprocal, log-product.
// XV0/XV1: inputs. UOv: float2 out. PP: row derivative product.
#define ROW_BODY(XV0, XV1, UOv, PP) {                                        \
    float _s0 = fsetge(XV0, thr00) + fsetge(XV0, thr01);                     \
    float _s1 = fsetge(XV0, thr02) + fsetge(XV0, thr03);                     \
    float _s2 = fsetge(XV0, thr04) + fsetge(XV0, thr05);                     \
    float _s3 = fsetge(XV0, thr06) + fsetge(XV0, thr07);                     \
    float _kf0 = fmaf(fsetge(XV0, thr08), -8.0f, (_s0 + _s1) + (_s2 + _s3)); \
    float _t0 = fsetge(XV1, thr10) + fsetge(XV1, thr11);                     \
    float _t1 = fsetge(XV1, thr12) + fsetge(XV1, thr13);                     \
    float _t2 = fsetge(XV1, thr14) + fsetge(XV1, thr15);                     \
    float _t3 = fsetge(XV1, thr16) + fsetge(XV1, thr17);                     \
    float _kf1 = fmaf(fsetge(XV1, thr18), -8.0f, (_t0 + _t1) + (_t2 + _t3)); \
    const int _i0 = __float2int_rz(_kf0) * DD + slotc0;                      \
    const int _i1 = __float2int_rz(_kf1) * DD + slotc1;                      \
    const float4 _A0 = sTA[_i0];  const float4 _B0 = sTB[_i0];               \
    const float4 _A1 = sTA[_i1];  const float4 _B1 = sTB[_i1];               \
    const float _th0 = fmaf(XV0, _A0.x, _A0.y);                              \
    const float _th1 = fmaf(XV1, _A1.x, _A1.y);                              \
    const float _q0  = fmaf(_th0, _B0.z, _B0.y);                             \
    const float _q1  = fmaf(_th1, _B1.z, _B1.y);                             \
    const float _n0  = (_A0.w * _th0) * _q0;                                 \
    const float _n1  = (_A1.w * _th1) * _q1;                                 \
    const float _e0  = _B0.w * _th0;                                         \
    const float _e1  = _B1.w * _th1;                                         \
    const float _d0  = fmaf(_e0, 1.0f - _th0, _B0.x);                        \
    const float _d1  = fmaf(_e1, 1.0f - _th1, _B1.x);                        \
    const float _invp = __fdividef(1.0f, _d0 * _d1);                         \
    const float _iv0 = _invp * _d1;                                          \
    const float _iv1 = _invp * _d0;                                          \
    (UOv).x = fmaf(_n0, _iv0, _A0.z);                                        \
    (UOv).y = fmaf(_n1, _iv1, _A1.z);                                        \
    const float _in0 = fmaf(_th0, fmaf(_B0.z, 2.0f, _e0), _B0.y);            \
    const float _in1 = fmaf(_th1, fmaf(_B1.z, 2.0f, _e1), _B1.y);            \
    const float _dd2 = (_B0.x * _B1.x) * _invp;                              \
    (PP) = (_dd2 * _dd2) * (_in0 * _in1);                                    \
}

// Process one quad (4 rows held in xq0..xq3), store u, park partials.
#define QUAD_BODY(PI) {                                                      \
    float2 uo0, uo1, uo2, uo3;                                               \
    float P0, P1, P2, P3;                                                    \
    ROW_BODY(xq0.x, xq0.y, uo0, P0);                                         \
    ROW_BODY(xq1.x, xq1.y, uo1, P1);                                         \
    ROW_BODY(xq2.x, xq2.y, uo2, P2);                                         \
    ROW_BODY(xq3.x, xq3.y, uo3, P3);                                         \
    *reinterpret_cast<float2*>(pu)          = uo0;                           \
    *reinterpret_cast<float2*>(pu + DD)     = uo1;                           \
    *reinterpret_cast<float2*>(pu + 2 * DD) = uo2;                           \
    *reinterpret_cast<float2*>(pu + 3 * DD) = uo3;                           \
    float la = __logf(P0), lb = __logf(P1);                                  \
    float lc = __logf(P2), ld = __logf(P3);                                  \
    la += __shfl_xor_sync(0xffffffffu, la, 16);                              \
    lb += __shfl_xor_sync(0xffffffffu, lb, 16);                              \
    lc += __shfl_xor_sync(0xffffffffu, lc, 16);                              \
    ld += __shfl_xor_sync(0xffffffffu, ld, 16);                              \
    la += __shfl_xor_sync(0xffffffffu, la, 8);                               \
    lb += __shfl_xor_sync(0xffffffffu, lb, 8);                               \
    lc += __shfl_xor_sync(0xffffffffu, lc, 8);                               \
    ld += __shfl_xor_sync(0xffffffffu, ld, 8);                               \
    la += __shfl_xor_sync(0xffffffffu, la, 4);                               \
    lb += __shfl_xor_sync(0xffffffffu, lb, 4);                               \
    lc += __shfl_xor_sync(0xffffffffu, lc, 4);                               \
    ld += __shfl_xor_sync(0xffffffffu, ld, 4);                               \
    if (lane < 4) {                                                          \
        float4* _p = reinterpret_cast<float4*>(                              \
            &sAux[PARTBASE(team, half, (PI)) + lane * 4]);                   \
        *_p = make_float4(la, lb, lc, ld);                                   \
    }                                                                        \
}

__global__ void __launch_bounds__(BLOCK, 2)
spline_kernel(const float* __restrict__ x,
              const float* __restrict__ uw,
              const float* __restrict__ uh,
              const float* __restrict__ ud,
              float* __restrict__ uout,
              float* __restrict__ ldout) {
    __shared__ float4 sTA[NSLOT * DD];   // 18 KB {invW, off, cumH, H}
    __shared__ float4 sTB[NSLOT * DD];   // 18 KB {delta, d0, g=delta-d0, e}
    __shared__ float  sAux[AUXN];        // 7 KB overlay

    const int tid  = threadIdx.x;
    const int lane = tid & 31;
    const int warp = tid >> 5;       // 0..15
    const int team = warp >> 1;      // 0..7
    const int half = warp & 1;       // which 64-dim half of the row

    // ---- per-block table build: thread dd (<128) builds dim dd ----
    if (tid < DD) {
        const float BOUND = 3.0f;
        const float MINW = 1e-3f, MINH = 1e-3f, MIND = 1e-3f, EPS = 1e-6f;
        const int dd = tid;

        float w[KK], h[KK];
        float m = -1e30f;
        #pragma unroll
        for (int k = 0; k < KK; k++) { w[k] = uw[dd * KK + k]; m = fmaxf(m, w[k]); }
        float s = 0.f;
        #pragma unroll
        for (int k = 0; k < KK; k++) { w[k] = expf(w[k] - m); s += w[k]; }
        float invs = 1.0f / s;
        #pragma unroll
        for (int k = 0; k < KK; k++) w[k] = MINW + (1.0f - MINW * KK) * (w[k] * invs);

        m = -1e30f;
        #pragma unroll
        for (int k = 0; k < KK; k++) { h[k] = uh[dd * KK + k]; m = fmaxf(m, h[k]); }
        s = 0.f;
        #pragma unroll
        for (int k = 0; k < KK; k++) { h[k] = expf(h[k] - m); s += h[k]; }
        invs = 1.0f / s;
        #pragma unroll
        for (int k = 0; k < KK; k++) h[k] = MINH + (1.0f - MINH * KK) * (h[k] * invs);

        float cw[KK + 1], ch[KK + 1];
        cw[0] = -BOUND; ch[0] = -BOUND;
        float accw = 0.f, acch = 0.f;
        #pragma unroll
        for (int k = 1; k < KK; k++) {
            accw += w[k - 1]; cw[k] = fmaf(2.0f * BOUND, accw, -BOUND);
            acch += h[k - 1]; ch[k] = fmaf(2.0f * BOUND, acch, -BOUND);
        }
        cw[KK] = BOUND; ch[KK] = BOUND;

        float dv[KK + 1];
        dv[0] = 1.0f - MIND; dv[KK] = 1.0f - MIND;
        #pragma unroll
        for (int k = 1; k < KK; k++) {
            float v = ud[dd * (KK - 1) + (k - 1)];
            dv[k] = MIND + fmaxf(v, 0.0f) + log1pf(expf(-fabsf(v)));
        }

        // slot remap: dim dd = hh*64 + 2*pos + c  ->  slot hh*64 + c*32 + pos
        const int hh  = dd >> 6;
        const int rem = dd & 63;
        const int s_slot = (hh << 6) + ((rem & 1) << 5) + (rem >> 1);

        // interior bins k -> slot k+1 (slots 1..8)
        #pragma unroll
        for (int k = 0; k < KK; k++) {
            float W = cw[k + 1] - cw[k];
            float H = ch[k + 1] - ch[k];
            float invW = 1.0f / W;
            float del  = H * invW;
            float d0 = dv[k], d1 = dv[k + 1];
            sTA[(k + 1) * DD + s_slot] = make_float4(invW, -cw[k] * invW, ch[k], H);
            sTB[(k + 1) * DD + s_slot] = make_float4(del, d0, del - d0,
                                                     d0 + d1 - 2.0f * del);
        }
        // identity slot 0 (both tails): u = x, derivative = 1
        sTA[0 * DD + s_slot] = make_float4(1.0f, 0.0f, 0.0f, 1.0f);
        sTB[0 * DD + s_slot] = make_float4(1.0f, 1.0f, 0.0f, 0.0f);

        // thresholds into overlay region
        sAux[0 * DD + s_slot] = -3.0f;
        #pragma unroll
        for (int t = 1; t < 8; t++) sAux[t * DD + s_slot] = cw[t] + EPS;
        sAux[8 * DD + s_slot] = __int_as_float(0x40400001);   // nextafter(3.0f)
    }
    __syncthreads();

    // ---- this lane's 2x9 thresholds into scalar registers ----
    const int slotc0 = (half << 6) + lane;
    const int slotc1 = slotc0 + 32;
    const float thr00 = sAux[0 * DD + slotc0], thr10 = sAux[0 * DD + slotc1];
    const float thr01 = sAux[1 * DD + slotc0], thr11 = sAux[1 * DD + slotc1];
    const float thr02 = sAux[2 * DD + slotc0], thr12 = sAux[2 * DD + slotc1];
    const float thr03 = sAux[3 * DD + slotc0], thr13 = sAux[3 * DD + slotc1];
    const float thr04 = sAux[4 * DD + slotc0], thr14 = sAux[4 * DD + slotc1];
    const float thr05 = sAux[5 * DD + slotc0], thr15 = sAux[5 * DD + slotc1];
    const float thr06 = sAux[6 * DD + slotc0], thr16 = sAux[6 * DD + slotc1];
    const float thr07 = sAux[7 * DD + slotc0], thr17 = sAux[7 * DD + slotc1];
    const float thr08 = sAux[8 * DD + slotc0], thr18 = sAux[8 * DD + slotc1];
    __syncthreads();   // overlay handoff: thresholds read; partials may write

    const int S = blockIdx.x * TEAMS + team;     // quad-stream id, 0..NSQ-1
    const int cnt = (NQ - S + NSQ - 1) / NSQ;    // 6 or 7 quads
    const size_t STEP = (size_t)NSQ * 512;       // floats per stream step
    const int coloff = (half << 6) + (lane << 1);

    const float* px = x + (size_t)S * 512 + coloff;
    float*       pu = uout + (size_t)S * 512 + coloff;
    float2 xq0 = *reinterpret_cast<const float2*>(px);
    float2 xq1 = *reinterpret_cast<const float2*>(px + DD);
    float2 xq2 = *reinterpret_cast<const float2*>(px + 2 * DD);
    float2 xq3 = *reinterpret_cast<const float2*>(px + 3 * DD);

    // main loop: cnt-1 iterations with unconditional prefetch
    for (int pi = 0; pi < cnt - 1; pi++) {
        const float2 xn0 = *reinterpret_cast<const float2*>(px + STEP);
        const float2 xn1 = *reinterpret_cast<const float2*>(px + STEP + DD);
        const float2 xn2 = *reinterpret_cast<const float2*>(px + STEP + 2 * DD);
        const float2 xn3 = *reinterpret_cast<const float2*>(px + STEP + 3 * DD);

        QUAD_BODY(pi);

        px += STEP;
        pu += STEP;
        xq0 = xn0; xq1 = xn1; xq2 = xn2; xq3 = xn3;
    }
    // peeled tail (no prefetch)
    QUAD_BODY(cnt - 1);

    __syncthreads();

    // ---- combine 8 partials per row (2 halves x 4 lane-groups) ----
    if (tid < TEAMS * MAXQ * 4) {
        const int tm  = tid / (MAXQ * 4);
        const int rem = tid - tm * (MAXQ * 4);
        const int qi  = rem >> 2;
        const int rb  = rem & 3;
        const int gq  = blockIdx.x * TEAMS + tm + qi * NSQ;
        if (gq < NQ) {
            float v = 0.f;
            #pragma unroll
            for (int hh = 0; hh < 2; hh++) {
                const int base = PARTBASE(tm, hh, qi);
                v += (sAux[base + 0 * 4 + rb] + sAux[base + 1 * 4 + rb]) +
                     (sAux[base + 2 * 4 + rb] + sAux[base + 3 * 4 + rb]);
            }
            ldout[4 * gq + rb] = v;
        }
    }
}

extern "C" void kernel_launch(void* const* d_in, const int* in_sizes, int n_in,
                              void* d_out, int out_size) {
    const float* x  = (const float*)d_in[0];
    const float* uw = (const float*)d_in[1];
    const float* uh = (const float*)d_in[2];
    const float* ud = (const float*)d_in[3];
    float* out = (float*)d_out;

    spline_kernel<<<GRIDB, BLOCK>>>(x, uw, uh, ud, out, out + (size_t)BB * DD);
}